// round 6
// baseline (speedup 1.0000x reference)
#include <cuda_runtime.h>
#include <cuda_bf16.h>
#include <mma.h>
#include <math.h>

#define N_NODES 50000
#define N_EDGES 800000
#define DD 32
#define HH 64
#define L_LAYERS 4
#define SPR 264          // padded smem row stride for 256-edge fp32 tiles (floats)

typedef unsigned long long ull;
typedef unsigned int uint;
typedef unsigned short ushort;

using namespace nvcuda;

// ---------------- scratch ----------------
__device__ float g_h[(size_t)N_NODES * DD];
__device__ float g_e[L_LAYERS + 1][(size_t)N_EDGES * DD];
__device__ float g_agg[(size_t)N_NODES * DD];

// ---------------- packed fp32x2 helpers ----------------
__device__ __forceinline__ ull pack2(float a, float b) {
    ull r; asm("mov.b64 %0,{%1,%2};" : "=l"(r) : "f"(a), "f"(b)); return r;
}
__device__ __forceinline__ float2 unpack2(ull v) {
    float2 r; asm("mov.b64 {%0,%1},%2;" : "=f"(r.x), "=f"(r.y) : "l"(v)); return r;
}
__device__ __forceinline__ void fma2(ull& d, ull a, ull b) {
    asm("fma.rn.f32x2 %0,%1,%2,%0;" : "+l"(d) : "l"(a), "l"(b));
}
__device__ __forceinline__ void red_add_v2(float* p, float x, float y) {
    asm volatile("red.global.add.v2.f32 [%0], {%1,%2};" :: "l"(p), "f"(x), "f"(y) : "memory");
}
__device__ __forceinline__ void coop_load(float* dst, const float* src, int n, int t, int nt) {
    for (int i = t; i < n; i += nt) dst[i] = src[i];
}

// ---------------- bf16 split helpers ----------------
__device__ __forceinline__ uint pack_bf16x2(float lo, float hi) {   // low half = bf16(lo)
    uint r; asm("cvt.rn.bf16x2.f32 %0, %1, %2;" : "=r"(r) : "f"(hi), "f"(lo)); return r;
}
__device__ __forceinline__ void split2(float x, float y, uint& h2, uint& l2) {
    h2 = pack_bf16x2(x, y);
    float hx = __uint_as_float(h2 << 16);
    float hy = __uint_as_float(h2 & 0xFFFF0000u);
    l2 = pack_bf16x2(x - hx, y - hy);
}
__device__ __forceinline__ void split1(float v, ushort& h, ushort& l) {
    asm("cvt.rn.bf16.f32 %0, %1;" : "=h"(h) : "f"(v));
    float hf = __uint_as_float((uint)h << 16);
    float r = v - hf;
    asm("cvt.rn.bf16.f32 %0, %1;" : "=h"(l) : "f"(r));
}

// ================= wmma relational kernel =================
// block = 128 edges, 256 threads (8 warps).
// A: bf16 [128][112] hi/lo.  W1 [96][72], W2 [64][72], W3 [64][40] hi/lo.  C f32 [128][72].
#define RA_STRIDE 112
#define RW_STRIDE 72
#define RW3_STRIDE 40
#define R_B1   0          // byte offsets
#define R_B2   256
#define R_B3   512
#define R_AHI  1024
#define R_ALO  (R_AHI + 128 * RA_STRIDE * 2)          // 29696
#define R_W1H  (R_ALO + 128 * RA_STRIDE * 2)          // 58368
#define R_W1L  (R_W1H + 96 * RW_STRIDE * 2)           // 72192
#define R_W2H  (R_W1L + 96 * RW_STRIDE * 2)           // 86016
#define R_W2L  (R_W2H + 64 * RW_STRIDE * 2)           // 95232
#define R_W3H  (R_W2L + 64 * RW_STRIDE * 2)           // 104448
#define R_W3L  (R_W3H + 64 * RW3_STRIDE * 2)          // 109568
#define R_C    (R_W3L + 64 * RW3_STRIDE * 2)          // 114688
#define R_SMEM (R_C + 128 * RW_STRIDE * 4)            // 151552

__global__ __launch_bounds__(256, 1) void rel_wmma_kernel(const int* __restrict__ ei, int layer,
        const float* __restrict__ W1, const float* __restrict__ b1,
        const float* __restrict__ W2, const float* __restrict__ b2,
        const float* __restrict__ W3, const float* __restrict__ b3) {
    extern __shared__ char smem[];
    float* sb1 = (float*)(smem + R_B1);
    float* sb2 = (float*)(smem + R_B2);
    float* sb3 = (float*)(smem + R_B3);
    __nv_bfloat16* Ah = (__nv_bfloat16*)(smem + R_AHI);
    __nv_bfloat16* Al = (__nv_bfloat16*)(smem + R_ALO);
    __nv_bfloat16* W1h = (__nv_bfloat16*)(smem + R_W1H);
    __nv_bfloat16* W1l = (__nv_bfloat16*)(smem + R_W1L);
    __nv_bfloat16* W2h = (__nv_bfloat16*)(smem + R_W2H);
    __nv_bfloat16* W2l = (__nv_bfloat16*)(smem + R_W2L);
    __nv_bfloat16* W3h = (__nv_bfloat16*)(smem + R_W3H);
    __nv_bfloat16* W3l = (__nv_bfloat16*)(smem + R_W3L);
    float* Cf = (float*)(smem + R_C);

    int t = threadIdx.x;
    int wid = t >> 5;
    int blk = blockIdx.x * 128;

    // ---- weight + bias fill (split bf16) ----
    for (int i = t; i < 6144; i += 256) {         // W1 96x64
        int k = i >> 6, n = i & 63;
        ushort h, l; split1(W1[i], h, l);
        *(ushort*)&W1h[k * RW_STRIDE + n] = h;
        *(ushort*)&W1l[k * RW_STRIDE + n] = l;
    }
    for (int i = t; i < 4096; i += 256) {         // W2 64x64
        int k = i >> 6, n = i & 63;
        ushort h, l; split1(W2[i], h, l);
        *(ushort*)&W2h[k * RW_STRIDE + n] = h;
        *(ushort*)&W2l[k * RW_STRIDE + n] = l;
    }
    for (int i = t; i < 2048; i += 256) {         // W3 64x32
        int k = i >> 5, n = i & 31;
        ushort h, l; split1(W3[i], h, l);
        *(ushort*)&W3h[k * RW3_STRIDE + n] = h;
        *(ushort*)&W3l[k * RW3_STRIDE + n] = l;
    }
    if (t < 64) sb1[t] = b1[t];
    else if (t < 128) sb2[t - 64] = b2[t - 64];
    else if (t < 160) sb3[t - 128] = b3[t - 128];

    // ---- activation gather + split: 2 threads per edge ----
    {
        int e = t >> 1, half = t & 1;
        int eid = blk + e;
        int s = ei[eid];
        int dn = ei[N_EDGES + eid];
        float v[48];
        if (half == 0) {
            const float4* hd = (const float4*)(g_h + (size_t)dn * DD);
            const float4* hs = (const float4*)(g_h + (size_t)s * DD);
#pragma unroll
            for (int q = 0; q < 8; q++) { float4 w = hd[q]; v[4*q]=w.x; v[4*q+1]=w.y; v[4*q+2]=w.z; v[4*q+3]=w.w; }
#pragma unroll
            for (int q = 0; q < 4; q++) { float4 w = hs[q]; v[32+4*q]=w.x; v[32+4*q+1]=w.y; v[32+4*q+2]=w.z; v[32+4*q+3]=w.w; }
        } else {
            const float4* hs = (const float4*)(g_h + (size_t)s * DD);
            const float4* ep = (const float4*)(g_e[layer] + (size_t)eid * DD);
#pragma unroll
            for (int q = 0; q < 4; q++) { float4 w = hs[4+q]; v[4*q]=w.x; v[4*q+1]=w.y; v[4*q+2]=w.z; v[4*q+3]=w.w; }
#pragma unroll
            for (int q = 0; q < 8; q++) { float4 w = ep[q]; v[16+4*q]=w.x; v[16+4*q+1]=w.y; v[16+4*q+2]=w.z; v[16+4*q+3]=w.w; }
        }
        uint* AhU = (uint*)Ah;
        uint* AlU = (uint*)Al;
        int base = e * (RA_STRIDE / 2) + half * 24;
#pragma unroll
        for (int c2 = 0; c2 < 24; c2++) {
            uint h2, l2; split2(v[2 * c2], v[2 * c2 + 1], h2, l2);
            AhU[base + c2] = h2;
            AlU[base + c2] = l2;
        }
    }
    __syncthreads();

    int m0 = wid * 16;

    // ---- layer 1: C = A[128x96] @ W1[96x64] ----
    {
        wmma::fragment<wmma::accumulator, 16, 16, 16, float> acc[4];
#pragma unroll
        for (int n = 0; n < 4; n++) wmma::fill_fragment(acc[n], 0.f);
#pragma unroll
        for (int kt = 0; kt < 6; kt++) {
            wmma::fragment<wmma::matrix_a, 16, 16, 16, __nv_bfloat16, wmma::row_major> aH, aL;
            wmma::load_matrix_sync(aH, Ah + m0 * RA_STRIDE + kt * 16, RA_STRIDE);
            wmma::load_matrix_sync(aL, Al + m0 * RA_STRIDE + kt * 16, RA_STRIDE);
#pragma unroll
            for (int n = 0; n < 4; n++) {
                wmma::fragment<wmma::matrix_b, 16, 16, 16, __nv_bfloat16, wmma::row_major> bH, bL;
                wmma::load_matrix_sync(bH, W1h + kt * 16 * RW_STRIDE + n * 16, RW_STRIDE);
                wmma::load_matrix_sync(bL, W1l + kt * 16 * RW_STRIDE + n * 16, RW_STRIDE);
                wmma::mma_sync(acc[n], aH, bH, acc[n]);
                wmma::mma_sync(acc[n], aH, bL, acc[n]);
                wmma::mma_sync(acc[n], aL, bH, acc[n]);
            }
        }
#pragma unroll
        for (int n = 0; n < 4; n++)
            wmma::store_matrix_sync(Cf + m0 * RW_STRIDE + n * 16, acc[n], RW_STRIDE, wmma::mem_row_major);
    }
    __syncthreads();

    // ---- bias + relu + split -> A (64 cols) ----
    {
        int r = t >> 1, c0 = (t & 1) * 32;
        uint* AhU = (uint*)Ah;
        uint* AlU = (uint*)Al;
        int base = r * (RA_STRIDE / 2) + c0 / 2;
#pragma unroll
        for (int c2 = 0; c2 < 16; c2++) {
            int col = c0 + 2 * c2;
            float x = fmaxf(Cf[r * RW_STRIDE + col] + sb1[col], 0.f);
            float y = fmaxf(Cf[r * RW_STRIDE + col + 1] + sb1[col + 1], 0.f);
            uint h2, l2; split2(x, y, h2, l2);
            AhU[base + c2] = h2;
            AlU[base + c2] = l2;
        }
    }
    __syncthreads();

    // ---- layer 2: C = A[128x64] @ W2[64x64] ----
    {
        wmma::fragment<wmma::accumulator, 16, 16, 16, float> acc[4];
#pragma unroll
        for (int n = 0; n < 4; n++) wmma::fill_fragment(acc[n], 0.f);
#pragma unroll
        for (int kt = 0; kt < 4; kt++) {
            wmma::fragment<wmma::matrix_a, 16, 16, 16, __nv_bfloat16, wmma::row_major> aH, aL;
            wmma::load_matrix_sync(aH, Ah + m0 * RA_STRIDE + kt * 16, RA_STRIDE);
            wmma::load_matrix_sync(aL, Al + m0 * RA_STRIDE + kt * 16, RA_STRIDE);
#pragma unroll
            for (int n = 0; n < 4; n++) {
                wmma::fragment<wmma::matrix_b, 16, 16, 16, __nv_bfloat16, wmma::row_major> bH, bL;
                wmma::load_matrix_sync(bH, W2h + kt * 16 * RW_STRIDE + n * 16, RW_STRIDE);
                wmma::load_matrix_sync(bL, W2l + kt * 16 * RW_STRIDE + n * 16, RW_STRIDE);
                wmma::mma_sync(acc[n], aH, bH, acc[n]);
                wmma::mma_sync(acc[n], aH, bL, acc[n]);
                wmma::mma_sync(acc[n], aL, bH, acc[n]);
            }
        }
        __syncthreads();   // layer-1 C fully consumed above before overwrite
#pragma unroll
        for (int n = 0; n < 4; n++)
            wmma::store_matrix_sync(Cf + m0 * RW_STRIDE + n * 16, acc[n], RW_STRIDE, wmma::mem_row_major);
    }
    __syncthreads();

    // ---- bias + relu + split -> A ----
    {
        int r = t >> 1, c0 = (t & 1) * 32;
        uint* AhU = (uint*)Ah;
        uint* AlU = (uint*)Al;
        int base = r * (RA_STRIDE / 2) + c0 / 2;
#pragma unroll
        for (int c2 = 0; c2 < 16; c2++) {
            int col = c0 + 2 * c2;
            float x = fmaxf(Cf[r * RW_STRIDE + col] + sb2[col], 0.f);
            float y = fmaxf(Cf[r * RW_STRIDE + col + 1] + sb2[col + 1], 0.f);
            uint h2, l2; split2(x, y, h2, l2);
            AhU[base + c2] = h2;
            AlU[base + c2] = l2;
        }
    }
    __syncthreads();

    // ---- layer 3: C = A[128x64] @ W3[64x32] ----
    {
        wmma::fragment<wmma::accumulator, 16, 16, 16, float> acc[2];
#pragma unroll
        for (int n = 0; n < 2; n++) wmma::fill_fragment(acc[n], 0.f);
#pragma unroll
        for (int kt = 0; kt < 4; kt++) {
            wmma::fragment<wmma::matrix_a, 16, 16, 16, __nv_bfloat16, wmma::row_major> aH, aL;
            wmma::load_matrix_sync(aH, Ah + m0 * RA_STRIDE + kt * 16, RA_STRIDE);
            wmma::load_matrix_sync(aL, Al + m0 * RA_STRIDE + kt * 16, RA_STRIDE);
#pragma unroll
            for (int n = 0; n < 2; n++) {
                wmma::fragment<wmma::matrix_b, 16, 16, 16, __nv_bfloat16, wmma::row_major> bH, bL;
                wmma::load_matrix_sync(bH, W3h + kt * 16 * RW3_STRIDE + n * 16, RW3_STRIDE);
                wmma::load_matrix_sync(bL, W3l + kt * 16 * RW3_STRIDE + n * 16, RW3_STRIDE);
                wmma::mma_sync(acc[n], aH, bH, acc[n]);
                wmma::mma_sync(acc[n], aH, bL, acc[n]);
                wmma::mma_sync(acc[n], aL, bH, acc[n]);
            }
        }
        __syncthreads();   // layer-2 C consumed
#pragma unroll
        for (int n = 0; n < 2; n++)
            wmma::store_matrix_sync(Cf + m0 * RW_STRIDE + n * 16, acc[n], RW_STRIDE, wmma::mem_row_major);
    }
    __syncthreads();

    // ---- epilogue: e_out = 0.5 e_in + 0.5 e_new ; agg[dst] += e_new ----
    if (t < 128) {
        int eid = blk + t;
        int dn = ei[N_EDGES + eid];
        float enew[32];
#pragma unroll
        for (int c = 0; c < 32; c++) enew[c] = Cf[t * RW_STRIDE + c] + sb3[c];
        const float4* ep = (const float4*)(g_e[layer] + (size_t)eid * DD);
        float* eo = g_e[layer + 1] + (size_t)eid * DD;
        float* ag = g_agg + (size_t)dn * DD;
#pragma unroll
        for (int q = 0; q < 8; q++) {
            float4 ein = ep[q];
            float4 o;
            o.x = 0.5f * ein.x + 0.5f * enew[4*q];
            o.y = 0.5f * ein.y + 0.5f * enew[4*q+1];
            o.z = 0.5f * ein.z + 0.5f * enew[4*q+2];
            o.w = 0.5f * ein.w + 0.5f * enew[4*q+3];
            *(float4*)&eo[4*q] = o;
        }
#pragma unroll
        for (int c = 0; c < 32; c += 2) red_add_v2(&ag[c], enew[c], enew[c + 1]);
    }
}

// ================= fp32 tiled kernels (unchanged) =================

__device__ __forceinline__ void st4col(float* smT, int row, int e, float4 v) {
    smT[(row + 0) * SPR + e] = v.x;
    smT[(row + 1) * SPR + e] = v.y;
    smT[(row + 2) * SPR + e] = v.z;
    smT[(row + 3) * SPR + e] = v.w;
}
template <int NU>
__device__ __forceinline__ void tile_fma(float4 a, const ull* __restrict__ wp, ull acc[4][NU]) {
    ull w[NU];
#pragma unroll
    for (int j = 0; j < NU; j++) w[j] = wp[j];
    ull a0 = pack2(a.x, a.x), a1 = pack2(a.y, a.y), a2 = pack2(a.z, a.z), a3 = pack2(a.w, a.w);
#pragma unroll
    for (int j = 0; j < NU; j++) {
        fma2(acc[0][j], a0, w[j]);
        fma2(acc[1][j], a1, w[j]);
        fma2(acc[2][j], a2, w[j]);
        fma2(acc[3][j], a3, w[j]);
    }
}
template <int NU>
__device__ __forceinline__ void init_bias(ull acc[4][NU], const float* b, int base) {
#pragma unroll
    for (int j = 0; j < NU; j++) {
        ull bj = pack2(b[base + 2 * j], b[base + 2 * j + 1]);
#pragma unroll
        for (int i = 0; i < 4; i++) acc[i][j] = bj;
    }
}
template <int NU>
__device__ __forceinline__ void init_zero_t(ull acc[4][NU]) {
#pragma unroll
    for (int j = 0; j < NU; j++)
#pragma unroll
        for (int i = 0; i < 4; i++) acc[i][j] = 0ull;
}
__device__ __forceinline__ float relu_sel(ull v, int hi) {
    float2 f = unpack2(v); return fmaxf(hi ? f.y : f.x, 0.f);
}
__device__ __forceinline__ void relu_writeT16(float* smT, ull acc[4][8], int og, int eg) {
#pragma unroll
    for (int cc = 0; cc < 16; cc++) {
        int j = cc >> 1, hi = cc & 1;
        float4 v;
        v.x = relu_sel(acc[0][j], hi);
        v.y = relu_sel(acc[1][j], hi);
        v.z = relu_sel(acc[2][j], hi);
        v.w = relu_sel(acc[3][j], hi);
        *(float4*)&smT[(og * 16 + cc) * SPR + 4 * eg] = v;
    }
}
template <int K, int NU>
__device__ __forceinline__ void mma_loop(const float* smT, const float* W, int wld, int wo,
                                         int eg, ull acc[4][NU]) {
#pragma unroll 2
    for (int k = 0; k < K; k++) {
        float4 a = *(const float4*)&smT[k * SPR + 4 * eg];
        tile_fma<NU>(a, (const ull*)&W[k * wld + wo], acc);
    }
}
template <int OUTP>
__device__ __forceinline__ void consume1(float a, const float* Wrow, ull* acc) {
    ull a2 = pack2(a, a);
    const ull* w = reinterpret_cast<const ull*>(Wrow);
#pragma unroll
    for (int j = 0; j < OUTP; j++) fma2(acc[j], a2, w[j]);
}
template <int OUTP>
__device__ __forceinline__ void init_zero(ull* acc) {
#pragma unroll
    for (int j = 0; j < OUTP; j++) acc[j] = 0ull;
}
template <int OUTP>
__device__ __forceinline__ void relu_store(const ull* acc, ull* s) {
#pragma unroll
    for (int j = 0; j < OUTP; j++) {
        float2 v = unpack2(acc[j]);
        s[j * 128] = pack2(fmaxf(v.x, 0.f), fmaxf(v.y, 0.f));
    }
}
template <int INP, int OUTP>
__device__ __forceinline__ void mlp_scratch(const ull* s, const float* W, ull* acc) {
#pragma unroll 1
    for (int p = 0; p < INP; p++) {
        float2 av = unpack2(s[p * 128]);
        consume1<OUTP>(av.x, W + (size_t)(2 * p) * (2 * OUTP), acc);
        consume1<OUTP>(av.y, W + (size_t)(2 * p + 1) * (2 * OUTP), acc);
    }
}

__global__ __launch_bounds__(128) void node_enc_kernel(const float* __restrict__ x,
                                                       const float* __restrict__ W1,
                                                       const float* __restrict__ W2) {
    extern __shared__ float sm[];
    float* sW1 = sm;
    float* sW2 = sm + 896;
    ull* scr = (ull*)(sm + 2944);
    int t = threadIdx.x;
    coop_load(sW1, W1, 896, t, 128);
    coop_load(sW2, W2, 2048, t, 128);
    __syncthreads();
    int n = blockIdx.x * 128 + t;
    if (n >= N_NODES) return;
    const float* xr = x + (size_t)n * 14;
    ull acc[32]; init_zero<32>(acc);
#pragma unroll 1
    for (int k = 0; k < 14; k++) consume1<32>(xr[k], sW1 + k * 64, acc);
    relu_store<32>(acc, scr + t);
    ull acc2[16]; init_zero<16>(acc2);
    mlp_scratch<32, 16>(scr + t, sW2, acc2);
    float4* ho = (float4*)(g_h + (size_t)n * DD);
#pragma unroll
    for (int q = 0; q < 8; q++) {
        float2 v0 = unpack2(acc2[2 * q]);
        float2 v1 = unpack2(acc2[2 * q + 1]);
        float4 o;
        o.x = fmaxf(v0.x, 0.f); o.y = fmaxf(v0.y, 0.f);
        o.z = fmaxf(v1.x, 0.f); o.w = fmaxf(v1.y, 0.f);
        ho[q] = o;
    }
}

__global__ __launch_bounds__(256, 2) void edge_enc_tile_kernel(const float* __restrict__ ea,
                                                               const float* __restrict__ W1,
                                                               const float* __restrict__ W2) {
    extern __shared__ float sm[];
    float* sW1 = sm;
    float* sW2 = sm + 256;
    float* smT = sm + 2304;
    int t = threadIdx.x;
    coop_load(sW1, W1, 256, t, 256);
    coop_load(sW2, W2, 2048, t, 256);
    int blk = blockIdx.x * 256;
    {
        float4 av = ((const float4*)ea)[blk + t];
        st4col(smT, 0, t, av);
    }
    __syncthreads();
    int eg = t & 63, og = t >> 6;
    ull acc[4][8];
    init_zero_t<8>(acc);
    mma_loop<4, 8>(smT, sW1, 64, og * 16, eg, acc);
    __syncthreads();
    relu_writeT16(smT, acc, og, eg);
    __syncthreads();
    ull acc3[4][4];
    init_zero_t<4>(acc3);
    mma_loop<64, 4>(smT, sW2, 32, og * 8, eg, acc3);
#pragma unroll
    for (int i = 0; i < 4; i++) {
        int eid_i = blk + 4 * eg + i;
#pragma unroll
        for (int j = 0; j < 4; j++) {
            int c = og * 8 + 2 * j;
            float2 v = unpack2(acc3[i][j]);
            float2 o; o.x = fmaxf(v.x, 0.f); o.y = fmaxf(v.y, 0.f);
            *(float2*)&g_e[0][(size_t)eid_i * DD + c] = o;
        }
    }
}

__global__ __launch_bounds__(256, 2) void obj_tile_kernel(const float* __restrict__ W1, const float* __restrict__ b1,
        const float* __restrict__ W2, const float* __restrict__ b2,
        const float* __restrict__ W3, const float* __restrict__ b3) {
    extern __shared__ float sm[];
    float* sW1 = sm;
    float* sW2 = sm + 4096;
    float* sW3 = sm + 8192;
    float* sb1 = sm + 10240;
    float* sb2 = sm + 10304;
    float* sb3 = sm + 10368;
    float* smT = sm + 10400;
    int t = threadIdx.x;
    coop_load(sW1, W1, 4096, t, 256);
    coop_load(sW2, W2, 4096, t, 256);
    coop_load(sW3, W3, 2048, t, 256);
    coop_load(sb1, b1, 64, t, 256);
    coop_load(sb2, b2, 64, t, 256);
    coop_load(sb3, b3, 32, t, 256);
    int blk = blockIdx.x * 256;
    {
        int n = blk + t;
        if (n < N_NODES) {
            const float4* hp = (const float4*)(g_h + (size_t)n * DD);
            const float4* ap = (const float4*)(g_agg + (size_t)n * DD);
#pragma unroll
            for (int q = 0; q < 8; q++) st4col(smT, 4 * q, t, hp[q]);
#pragma unroll
            for (int q = 0; q < 8; q++) st4col(smT, 32 + 4 * q, t, ap[q]);
        }
    }
    __syncthreads();
    int eg = t & 63, og = t >> 6;
    ull acc[4][8];
    init_bias<8>(acc, sb1, og * 16);
    mma_loop<64, 8>(smT, sW1, 64, og * 16, eg, acc);
    __syncthreads();
    relu_writeT16(smT, acc, og, eg);
    __syncthreads();
    init_bias<8>(acc, sb2, og * 16);
    mma_loop<64, 8>(smT, sW2, 64, og * 16, eg, acc);
    __syncthreads();
    relu_writeT16(smT, acc, og, eg);
    __syncthreads();
    ull acc3[4][4];
    init_bias<4>(acc3, sb3, og * 8);
    mma_loop<64, 4>(smT, sW3, 32, og * 8, eg, acc3);
#pragma unroll
    for (int i = 0; i < 4; i++) {
        int n_i = blk + 4 * eg + i;
        if (n_i < N_NODES) {
#pragma unroll
            for (int j = 0; j < 4; j++) {
                int c = og * 8 + 2 * j;
                float2 v = unpack2(acc3[i][j]);
                float2 hold = *(float2*)&g_h[(size_t)n_i * DD + c];
                float2 o;
                o.x = 0.5f * hold.x + 0.5f * v.x;
                o.y = 0.5f * hold.y + 0.5f * v.y;
                *(float2*)&g_h[(size_t)n_i * DD + c] = o;
            }
        }
    }
}

__global__ __launch_bounds__(256, 1) void final_tile_kernel(const int* __restrict__ ei,
        const float* __restrict__ W1, const float* __restrict__ b1,
        const float* __restrict__ W2, const float* __restrict__ b2,
        const float* __restrict__ W3, const float* __restrict__ b3,
        float* __restrict__ out) {
    extern __shared__ float sm[];
    float* sW1 = sm;
    float* sW2 = sm + 6144;
    float* sW3 = sm + 10240;
    float* sb1 = sm + 10304;
    float* sb2 = sm + 10368;
    float* sb3 = sm + 10432;
    float* smT = sm + 10436;
    int t = threadIdx.x;
    coop_load(sW1, W1, 6144, t, 256);
    coop_load(sW2, W2, 4096, t, 256);
    coop_load(sW3, W3, 64, t, 256);
    coop_load(sb1, b1, 64, t, 256);
    coop_load(sb2, b2, 64, t, 256);
    if (t == 0) sb3[0] = b3[0];
    int blk = blockIdx.x * 256;
    int eid = blk + t;
    int s = ei[eid];
    int d = ei[N_EDGES + eid];
    {
        const float4* hs = (const float4*)(g_h + (size_t)s * DD);
        const float4* hd = (const float4*)(g_h + (size_t)d * DD);
        const float4* e1 = (const float4*)(g_e[1] + (size_t)eid * DD);
#pragma unroll
        for (int q = 0; q < 8; q++) st4col(smT, 4 * q, t, hs[q]);
#pragma unroll
        for (int q = 0; q < 8; q++) st4col(smT, 32 + 4 * q, t, hd[q]);
#pragma unroll
        for (int q = 0; q < 8; q++) st4col(smT, 64 + 4 * q, t, e1[q]);
    }
    __syncthreads();
    int eg = t & 63, og = t >> 6;
    ull acc[4][8];
    init_bias<8>(acc, sb1, og * 16);
    mma_loop<96, 8>(smT, sW1, 64, og * 16, eg, acc);
    __syncthreads();
    {
        const float4* e2 = (const float4*)(g_e[2] + (size_t)eid * DD);
        const float4* e3 = (const float4*)(g_e[3] + (size_t)eid * DD);
        const float4* e4 = (const float4*)(g_e[4] + (size_t)eid * DD);
#pragma unroll
        for (int q = 0; q < 8; q++) st4col(smT, 4 * q, t, e2[q]);
#pragma unroll
        for (int q = 0; q < 8; q++) st4col(smT, 32 + 4 * q, t, e3[q]);
#pragma unroll
        for (int q = 0; q < 8; q++) st4col(smT, 64 + 4 * q, t, e4[q]);
    }
    coop_load(sW1, W1 + 96 * 64, 6144, t, 256);
    __syncthreads();
    mma_loop<96, 8>(smT, sW1, 64, og * 16, eg, acc);
    __syncthreads();
    relu_writeT16(smT, acc, og, eg);
    __syncthreads();
    init_bias<8>(acc, sb2, og * 16);
    mma_loop<64, 8>(smT, sW2, 64, og * 16, eg, acc);
    __syncthreads();
    relu_writeT16(smT, acc, og, eg);
    __syncthreads();
    {
        float logit = sb3[0];
#pragma unroll 2
        for (int k = 0; k < 64; k++) logit += smT[k * SPR + t] * sW3[k];
        float sig = 1.f / (1.f + expf(-logit));
        out[eid] = 1e-3f + (1.f - 2e-3f) * sig;
    }
}

__global__ void zero_agg_kernel() {
    int i = blockIdx.x * 256 + threadIdx.x;
    if (i < N_NODES * DD) g_agg[i] = 0.f;
}

__global__ void writeback_kernel(float* __restrict__ out) {
    size_t i = (size_t)blockIdx.x * 256 + threadIdx.x;
    if (i < (size_t)N_NODES * DD) out[(size_t)N_EDGES + i] = g_h[i];
    if (i < (size_t)N_EDGES * DD) out[(size_t)N_EDGES + (size_t)N_NODES * DD + i] = g_e[4][i];
}

// ---------------- launch ----------------
extern "C" void kernel_launch(void* const* d_in, const int* in_sizes, int n_in,
                              void* d_out, int out_size) {
    const float* x      = (const float*)d_in[0];
    const int*   ei     = (const int*)d_in[1];
    const float* ea     = (const float*)d_in[2];
    const float* enW1   = (const float*)d_in[3];
    const float* enW2   = (const float*)d_in[4];
    const float* eeW1   = (const float*)d_in[5];
    const float* eeW2   = (const float*)d_in[6];
    const float* rW1    = (const float*)d_in[7];
    const float* rb1    = (const float*)d_in[8];
    const float* rW2    = (const float*)d_in[9];
    const float* rb2    = (const float*)d_in[10];
    const float* rW3    = (const float*)d_in[11];
    const float* rb3    = (const float*)d_in[12];
    const float* oW1    = (const float*)d_in[13];
    const float* ob1    = (const float*)d_in[14];
    const float* oW2    = (const float*)d_in[15];
    const float* ob2    = (const float*)d_in[16];
    const float* oW3    = (const float*)d_in[17];
    const float* ob3    = (const float*)d_in[18];
    const float* wW1    = (const float*)d_in[19];
    const float* wb1    = (const float*)d_in[20];
    const float* wW2    = (const float*)d_in[21];
    const float* wb2    = (const float*)d_in[22];
    const float* wW3    = (const float*)d_in[23];
    const float* wb3    = (const float*)d_in[24];
    float* out = (float*)d_out;

    const int NODE_SMEM = 2944 * 4 + 128 * 32 * 8;
    const int EE_SMEM   = (2304 + 64 * SPR) * 4;
    const int OBJ_SMEM  = (10400 + 64 * SPR) * 4;
    const int FIN_SMEM  = (10436 + 96 * SPR) * 4;

    cudaFuncSetAttribute(node_enc_kernel, cudaFuncAttributeMaxDynamicSharedMemorySize, NODE_SMEM);
    cudaFuncSetAttribute(edge_enc_tile_kernel, cudaFuncAttributeMaxDynamicSharedMemorySize, EE_SMEM);
    cudaFuncSetAttribute(rel_wmma_kernel, cudaFuncAttributeMaxDynamicSharedMemorySize, R_SMEM);
    cudaFuncSetAttribute(obj_tile_kernel, cudaFuncAttributeMaxDynamicSharedMemorySize, OBJ_SMEM);
    cudaFuncSetAttribute(final_tile_kernel, cudaFuncAttributeMaxDynamicSharedMemorySize, FIN_SMEM);

    int nodeBlocks = (N_NODES + 127) / 128;
    int objBlocks  = (N_NODES + 255) / 256;
    int tileBlocks256 = N_EDGES / 256;     // 3125
    int relBlocks = N_EDGES / 128;         // 6250

    node_enc_kernel<<<nodeBlocks, 128, NODE_SMEM>>>(x, enW1, enW2);
    edge_enc_tile_kernel<<<tileBlocks256, 256, EE_SMEM>>>(ea, eeW1, eeW2);

    for (int l = 0; l < L_LAYERS; l++) {
        zero_agg_kernel<<<(N_NODES * DD + 255) / 256, 256>>>();
        rel_wmma_kernel<<<relBlocks, 256, R_SMEM>>>(ei, l,
            rW1 + (size_t)l * 96 * 64, rb1 + (size_t)l * 64,
            rW2 + (size_t)l * 64 * 64, rb2 + (size_t)l * 64,
            rW3 + (size_t)l * 64 * 32, rb3 + (size_t)l * 32);
        obj_tile_kernel<<<objBlocks, 256, OBJ_SMEM>>>(
            oW1 + (size_t)l * 64 * 64, ob1 + (size_t)l * 64,
            oW2 + (size_t)l * 64 * 64, ob2 + (size_t)l * 64,
            oW3 + (size_t)l * 64 * 32, ob3 + (size_t)l * 32);
    }

    final_tile_kernel<<<tileBlocks256, 256, FIN_SMEM>>>(ei, wW1, wb1, wW2, wb2, wW3, wb3, out);

    writeback_kernel<<<((size_t)N_EDGES * DD + 255) / 256, 256>>>(out);
}